// round 4
// baseline (speedup 1.0000x reference)
#include <cuda_runtime.h>
#include <math.h>
#include <cstdint>

#define B 2
#define NPROP 1000
#define NCLS 81
#define MASK_ELEMS (28*28*81)      // 63504 floats per proposal mask
#define MASK_V4 (MASK_ELEMS/4)     // 15876 float4
#define MAXI 100
#define NMS_THR 0.3f
#define MIN_CONF 0.5f

// ---------------- scratch (device globals; no allocation allowed) ------------
__device__ float        g_refined[B][NPROP][4];
__device__ float        g_score[B][NPROP];
__device__ int          g_cid[B][NPROP];
__device__ unsigned char g_keep0[B][NPROP];
__device__ unsigned char g_nms[B][NPROP];
__device__ int          g_slot[B][MAXI];
__device__ int          g_kcount[B];

// ---------------- stage 1: argmax + box refine + clip ------------------------
__global__ void prep_kernel(const float* __restrict__ rois,
                            const float* __restrict__ probs,
                            const float* __restrict__ deltas,
                            const float* __restrict__ window) {
    int idx = blockIdx.x * blockDim.x + threadIdx.x;
    if (idx >= B * NPROP) return;
    int b = idx / NPROP, i = idx % NPROP;

    const float* p = probs + (size_t)idx * NCLS;
    float best = p[0]; int cid = 0;
    #pragma unroll 4
    for (int c = 1; c < NCLS; c++) {
        float v = p[c];
        if (v > best) { best = v; cid = c; }   // first-occurrence argmax (strict >)
    }

    const float* r = rois + (size_t)idx * 4;
    float r0 = r[0], r1 = r[1], r2 = r[2], r3 = r[3];
    bool valid = (fabsf(r0) + fabsf(r1) + fabsf(r2) + fabsf(r3)) > 0.0f;

    const float* dl = deltas + ((size_t)idx * NCLS + cid) * 4;
    float dy = dl[0] * 0.1f, dx = dl[1] * 0.1f;
    float dh = dl[2] * 0.2f, dw = dl[3] * 0.2f;

    float h = r2 - r0, w = r3 - r1;
    float cy = r0 + 0.5f * h + dy * h;
    float cx = r1 + 0.5f * w + dx * w;
    h = h * expf(dh);
    w = w * expf(dw);
    float y1 = cy - 0.5f * h, x1 = cx - 0.5f * w;
    float y2 = cy + 0.5f * h, x2 = cx + 0.5f * w;

    float wy1 = window[0], wx1 = window[1], wy2 = window[2], wx2 = window[3];
    y1 = fminf(fmaxf(y1, wy1), wy2);
    x1 = fminf(fmaxf(x1, wx1), wx2);
    y2 = fminf(fmaxf(y2, wy1), wy2);
    x2 = fminf(fmaxf(x2, wx1), wx2);

    g_refined[b][i][0] = y1; g_refined[b][i][1] = x1;
    g_refined[b][i][2] = y2; g_refined[b][i][3] = x2;
    g_score[b][i] = best;
    g_cid[b][i]   = cid;
    g_keep0[b][i] = (valid && cid > 0 && best >= MIN_CONF) ? 1 : 0;
    g_nms[b][i]   = 0;
}

// ---------------- stage 2: per-class NMS, one block per batch -----------------
// 32 warps; classes 1..80 strided across warps. Per class: lanes collect
// candidates via ballot-compaction (index order preserved -> stable), then
// lane 0 runs greedy NMS in (score desc, idx asc) order.
__global__ __launch_bounds__(1024) void nms_kernel() {
    int b = blockIdx.x;
    int wid = threadIdx.x / 32;
    int lid = threadIdx.x % 32;

    // cache boxes+scores+cid in shared
    __shared__ float4 s_box[NPROP];
    __shared__ float  s_sc[NPROP];
    __shared__ short  s_cd[NPROP];     // cid if keep0 else -1
    for (int i = threadIdx.x; i < NPROP; i += 1024) {
        s_box[i] = *(const float4*)&g_refined[b][i][0];
        s_sc[i]  = g_score[b][i];
        s_cd[i]  = g_keep0[b][i] ? (short)g_cid[b][i] : (short)-1;
    }
    __syncthreads();

    for (int c = 1 + wid; c < NCLS; c += 32) {
        // collect candidate indices (ascending) per lane region
        int cand[64]; float csc[64];
        int k = 0;
        for (int base = 0; base < NPROP; base += 32) {
            int i = base + lid;
            bool hit = (i < NPROP) && (s_cd[i] == (short)c);
            unsigned m = __ballot_sync(0xFFFFFFFFu, hit);
            // each lane appends the hits in order
            while (m) {
                int src = __ffs(m) - 1;
                int ii = base + src;
                if (k < 64) { cand[k] = ii; csc[k] = s_sc[ii]; k++; }
                m &= m - 1;
            }
        }
        // every lane has identical cand/csc lists; lane 0 does greedy
        if (lid == 0 && k > 0) {
            // selection order: score desc, idx asc; greedy with kept-list
            float kb[64][4]; int nk = 0;
            unsigned long long used = 0;
            for (int step = 0; step < k && nk < MAXI; step++) {
                int bestA = -1; float bs = -1e30f;
                for (int a = 0; a < k; a++) {
                    if (used >> a & 1ull) continue;
                    if (csc[a] > bs) { bs = csc[a]; bestA = a; }
                }
                if (bestA < 0) break;
                used |= 1ull << bestA;
                int i = cand[bestA];
                float4 bx = s_box[i];
                float area = (bx.z - bx.x) * (bx.w - bx.y);
                bool sup = false;
                for (int t = 0; t < nk; t++) {
                    float iy1 = fmaxf(kb[t][0], bx.x), ix1 = fmaxf(kb[t][1], bx.y);
                    float iy2 = fminf(kb[t][2], bx.z), ix2 = fminf(kb[t][3], bx.w);
                    float inter = fmaxf(iy2 - iy1, 0.0f) * fmaxf(ix2 - ix1, 0.0f);
                    float ka = (kb[t][2] - kb[t][0]) * (kb[t][3] - kb[t][1]);
                    float iou = inter / (ka + area - inter + 1e-8f);
                    if (iou > NMS_THR) { sup = true; break; }
                }
                if (!sup) {
                    kb[nk][0] = bx.x; kb[nk][1] = bx.y; kb[nk][2] = bx.z; kb[nk][3] = bx.w;
                    nk++;
                    g_nms[b][i] = 1;
                }
            }
        }
    }
}

// ---------------- stage 3: stable top-k + det rows (fused) --------------------
__global__ void topk_det_kernel(float* __restrict__ out) {
    int b = blockIdx.x;
    __shared__ float s_s[NPROP];
    __shared__ unsigned char s_f[NPROP];
    __shared__ int s_slot[MAXI];
    __shared__ int kc;
    if (threadIdx.x == 0) kc = 0;
    __syncthreads();

    int local = 0;
    for (int i = threadIdx.x; i < NPROP; i += blockDim.x) {
        unsigned char f = (g_keep0[b][i] && g_nms[b][i]) ? 1 : 0;
        s_f[i] = f;
        s_s[i] = g_score[b][i];
        local += f;
    }
    atomicAdd(&kc, local);
    __syncthreads();
    int kcc = min(kc, MAXI);

    for (int i = threadIdx.x; i < NPROP; i += blockDim.x) {
        if (s_f[i]) {
            float si = s_s[i];
            int r = 0;
            for (int j = 0; j < NPROP; j++)
                r += (s_f[j] && ((s_s[j] > si) || (s_s[j] == si && j < i))) ? 1 : 0;
            if (r < MAXI) s_slot[r] = i;
        } else {
            int r = 0;
            for (int j = 0; j < i; j++) r += (s_f[j] == 0) ? 1 : 0;
            int s = kcc + r;
            if (s < MAXI) s_slot[s] = i;
        }
    }
    __syncthreads();

    if (threadIdx.x < MAXI) g_slot[b][threadIdx.x] = s_slot[threadIdx.x];
    if (threadIdx.x == 0) g_kcount[b] = kcc;

    int s = threadIdx.x;
    if (s < MAXI) {
        float* o = out + ((size_t)b * MAXI + s) * 6;
        if (s < kcc) {
            int i = s_slot[s];
            o[0] = g_refined[b][i][0];
            o[1] = g_refined[b][i][1];
            o[2] = g_refined[b][i][2];
            o[3] = g_refined[b][i][3];
            o[4] = (float)g_cid[b][i];
            o[5] = s_s[i];
        } else {
            o[0] = 0.f; o[1] = 0.f; o[2] = 0.f; o[3] = 0.f; o[4] = 0.f; o[5] = 0.f;
        }
    }
}

// ---------------- stage 4: 5-D broadcast mask write via TMA bulk stores -------
// out[b,i,j,:] = (i < kcount[b]) ? masks[b, slot[j], :] : 0
// Single SMEM buffer (data only); rows i >= kc handled by zerotail_kernel.
#define CHUNK_V4 1024          // float4 per block-chunk (16 KB)
#define NCHUNK   16            // ceil(15876 / 1024)

__device__ __forceinline__ uint32_t smem_u32(const void* p) {
    uint32_t a;
    asm("{ .reg .u64 t; cvta.to.shared.u64 t, %1; cvt.u32.u64 %0, t; }"
        : "=r"(a) : "l"(p));
    return a;
}

__global__ __launch_bounds__(256) void mask5d_tma_kernel(
        const float* __restrict__ masks, float* __restrict__ out) {
    __shared__ alignas(128) float4 s_data[CHUNK_V4];

    int b = blockIdx.z;
    int j = blockIdx.y;
    int chunk0 = blockIdx.x * CHUNK_V4;
    int n_v4 = MASK_V4 - chunk0; if (n_v4 > CHUNK_V4) n_v4 = CHUNK_V4;

    int kc   = g_kcount[b];
    int slot = g_slot[b][j];

    const float4* src = (const float4*)(masks + (size_t)(b * NPROP + slot) * MASK_ELEMS)
                        + chunk0;
    for (int t = threadIdx.x; t < n_v4; t += 256)
        s_data[t] = __ldg(&src[t]);
    __syncthreads();
    asm volatile("fence.proxy.async.shared::cta;" ::: "memory");

    if (threadIdx.x == 0) {
        uint32_t sa_data = smem_u32(s_data);
        char* dst = (char*)((float4*)(out + (size_t)B * MAXI * 6)
                    + ((size_t)(b * MAXI) * MAXI + j) * MASK_V4 + chunk0);
        const size_t istride = (size_t)MAXI * MASK_V4 * 16;
        const int bytes = n_v4 * 16;

        for (int i = 0; i < kc; i++) {
            asm volatile(
                "cp.async.bulk.global.shared::cta.bulk_group [%0], [%1], %2;"
                :: "l"(dst), "r"(sa_data), "r"(bytes) : "memory");
            dst += istride;
        }
        asm volatile("cp.async.bulk.commit_group;" ::: "memory");
        asm volatile("cp.async.bulk.wait_group 0;" ::: "memory");
    }
    __syncthreads();   // SMEM must stay alive until TMA reads complete
}

// zero rows i in [kc, MAXI): contiguous per batch; early-exit when kc==MAXI
__global__ void zerotail_kernel(float* __restrict__ out) {
    int b = blockIdx.y;
    int kc = g_kcount[b];
    if (kc >= MAXI) return;
    size_t row0   = ((size_t)b * MAXI + kc) * MAXI;      // first zero (i,j) row
    size_t nrows  = (size_t)(MAXI - kc) * MAXI;
    size_t total  = nrows * MASK_V4;
    float4* base  = (float4*)(out + (size_t)B * MAXI * 6) + row0 * MASK_V4;
    const float4 z = make_float4(0.f, 0.f, 0.f, 0.f);
    for (size_t e = (size_t)blockIdx.x * blockDim.x + threadIdx.x;
         e < total; e += (size_t)gridDim.x * blockDim.x)
        __stcs(&base[e], z);
}

// ---------------- 4-D fallback (defensive) ------------------------------------
__global__ void mask4d_kernel(const float* __restrict__ masks, float* __restrict__ out) {
    long long e = (long long)blockIdx.x * blockDim.x + threadIdx.x;
    long long total = (long long)B * MAXI * MASK_V4;
    if (e >= total) return;
    int row = (int)(e / MASK_V4);
    int w   = (int)(e % MASK_V4);
    int b = row / MAXI, s = row % MAXI;
    float4 v = make_float4(0.f, 0.f, 0.f, 0.f);
    if (s < g_kcount[b]) {
        int i = g_slot[b][s];
        const float4* src = (const float4*)(masks + (size_t)(b * NPROP + i) * MASK_ELEMS);
        v = src[w];
    }
    float4* dst = (float4*)(out + (size_t)B * MAXI * 6);
    dst[e] = v;
}

// ---------------- launch ------------------------------------------------------
extern "C" void kernel_launch(void* const* d_in, const int* in_sizes, int n_in,
                              void* d_out, int out_size) {
    const float* rois   = (const float*)d_in[0];
    const float* probs  = (const float*)d_in[1];
    const float* deltas = (const float*)d_in[2];
    const float* masks  = (const float*)d_in[3];
    const float* window = (const float*)d_in[4];
    float* out = (float*)d_out;

    prep_kernel<<<(B * NPROP + 255) / 256, 256>>>(rois, probs, deltas, window);
    nms_kernel<<<B, 1024>>>();
    topk_det_kernel<<<B, 256>>>(out);

    long long det_elems  = (long long)B * MAXI * 6;
    long long mask_elems = (long long)out_size - det_elems;
    long long rows = mask_elems / MASK_ELEMS;

    if (rows >= (long long)B * MAXI * MAXI) {
        dim3 grid(NCHUNK, MAXI, B);
        mask5d_tma_kernel<<<grid, 256>>>(masks, out);
        dim3 zgrid(512, B);
        zerotail_kernel<<<zgrid, 256>>>(out);
    } else {
        long long total = (long long)B * MAXI * MASK_V4;
        int gridn = (int)((total + 255) / 256);
        mask4d_kernel<<<gridn, 256>>>(masks, out);
    }
}